// round 5
// baseline (speedup 1.0000x reference)
#include <cuda_runtime.h>

// Path signature, depth 3. path: (32, 128, 48) fp32. Out: 32 x 112944.
//
// S3[i,j,k] = sum_t w[i][t][j] * v[t][k]
//   v[t][j]    = path[t+1][j] - path[t][j]
//   w[i][t][j] = S2prev[i][j] + (0.5*S1prev[i] + v[t][i]/6) * v[t][j]
//   S2[i][j]  += (S1prev[i] + 0.5*v[t][i]) * v[t][j]
//
// Block (bx,b): two i-planes, two 48x48 (j,k) reg tiles, 144 threads,
// 4x4 tile per thread per plane. Inner product uses packed fma.rn.f32x2
// with accumulators paired along j (w pairs come free from the 16B shared
// loads; v lane-duplicated via mov.b64). T=8 chunking, double-buffered
// v/w, one barrier per chunk. Phase-B t-unroll capped at 4 to bound the
// number of in-flight LDS registers (anti-spill).

#define NB     32
#define LPATH  128
#define C      48
#define NSTEPS (LPATH - 1)          // 127
#define LVL2   (C * C)
#define LVL3   (C * C * C)
#define STR    (C + LVL2 + LVL3)    // 112944
#define OFF2   C
#define OFF3   (C + LVL2)
#define TCH    8

typedef unsigned long long u64;

__device__ __forceinline__ void ffma2(u64& d, u64 a, u64 b) {
    asm("fma.rn.f32x2 %0, %1, %2, %0;" : "+l"(d) : "l"(a), "l"(b));
}
__device__ __forceinline__ u64 dup_f32(float x) {
    u64 r;
    asm("mov.b64 %0, {%1, %1};" : "=l"(r) : "f"(x));
    return r;
}
__device__ __forceinline__ float2 unpk(u64 a) {
    float2 r;
    asm("mov.b64 {%0, %1}, %2;" : "=f"(r.x), "=f"(r.y) : "l"(a));
    return r;
}

template<int T>
__device__ __forceinline__ void do_chunk(
    const float* __restrict__ pb, int base_t, int buf, int i_r, int r, int jj,
    int tid, u64 (&acc0)[2][4], u64 (&acc1)[2][4], int j0, int k0,
    float& p_j, float& p_i, float p0_i, float& S2,
    float (*sh_v)[TCH][C], float (*sh_w)[2][TCH][C])
{
    // ---- Phase A: threads 0..95 (3 warps); group r makes w-row for i_r ----
    if (tid < 2 * C) {
#pragma unroll
        for (int t = 0; t < T; ++t) {
            const float pn_j = pb[(base_t + t + 1) * C + jj];  // coalesced
            const float pn_i = pb[(base_t + t + 1) * C + i_r]; // broadcast
            const float v_j = pn_j - p_j;
            const float v_i = pn_i - p_i;
            const float s1  = p_i - p0_i;
            if (r == 0) sh_v[buf][t][jj] = v_j;
            sh_w[buf][r][t][jj] = fmaf(fmaf(1.0f / 6.0f, v_i, 0.5f * s1), v_j, S2);
            S2 = fmaf(fmaf(0.5f, v_i, s1), v_j, S2);
            p_j = pn_j;
            p_i = pn_i;
        }
    }
    __syncthreads();
    // One barrier per chunk is safe with double buffering: phase B of chunk c
    // precedes (program order) the barrier of chunk c+1, so by the time phase
    // A of chunk c+2 reuses this buffer, every reader of chunk c has passed.

    // ---- Phase B: T rank-1 updates of both tiles, packed f32x2.
    //      Unroll capped at 4 to limit in-flight LDS destination registers. ----
#pragma unroll 4
    for (int t = 0; t < T; ++t) {
        const ulonglong2 w0 = *(const ulonglong2*)&sh_w[buf][0][t][j0];
        const ulonglong2 w1 = *(const ulonglong2*)&sh_w[buf][1][t][j0];
        const float4     vv = *(const float4*)&sh_v[buf][t][k0];
        const u64 vp[4] = { dup_f32(vv.x), dup_f32(vv.y),
                            dup_f32(vv.z), dup_f32(vv.w) };
        const u64 wa[2] = { w0.x, w0.y };   // (w[j0],w[j0+1]), (w[j0+2],w[j0+3])
        const u64 wb[2] = { w1.x, w1.y };
#pragma unroll
        for (int jp = 0; jp < 2; ++jp)
#pragma unroll
            for (int kx = 0; kx < 4; ++kx) {
                ffma2(acc0[jp][kx], wa[jp], vp[kx]);
                ffma2(acc1[jp][kx], wb[jp], vp[kx]);
            }
    }
}

__global__ __launch_bounds__(144, 6)
void sig_depth3_kernel(const float* __restrict__ path, float* __restrict__ out)
{
    const int bx  = blockIdx.x;   // 0..23 -> i0 = 2bx, i1 = 2bx+1
    const int b   = blockIdx.y;   // 0..31
    const int tid = threadIdx.x;  // 0..143

    __shared__ __align__(16) float sh_v[2][TCH][C];
    __shared__ __align__(16) float sh_w[2][2][TCH][C];

    const float* pb = path + (size_t)b * LPATH * C;

    // acc[jp][kx]: f32x2 pair = rows (j0+2jp, j0+2jp+1), column k0+kx
    u64 acc0[2][4], acc1[2][4];
#pragma unroll
    for (int jp = 0; jp < 2; ++jp)
#pragma unroll
        for (int kx = 0; kx < 4; ++kx) { acc0[jp][kx] = 0ull; acc1[jp][kx] = 0ull; }

    const int j0 = (tid / 12) * 4;
    const int k0 = (tid % 12) * 4;

    const int r   = (tid < C) ? 0 : 1;
    const int jj  = tid - r * C;             // 0..47 within group
    const int i_r = 2 * bx + r;

    float p_j = 0.0f, p_i = 0.0f, p0_i = 0.0f, S2 = 0.0f;
    if (tid < 2 * C) {
        p_j  = pb[jj];
        p0_i = pb[i_r];
        p_i  = p0_i;
    }

    int base_t = 0;
#pragma unroll 1
    for (int ch = 0; ch < 15; ++ch) {        // 15 chunks of 8 = 120 steps
        do_chunk<TCH>(pb, base_t, ch & 1, i_r, r, jj, tid, acc0, acc1,
                      j0, k0, p_j, p_i, p0_i, S2, sh_v, sh_w);
        base_t += TCH;
    }
    do_chunk<NSTEPS - 15 * TCH>(pb, base_t, 15 & 1, i_r, r, jj, tid,  // tail 7
                                acc0, acc1, j0, k0, p_j, p_i, p0_i, S2,
                                sh_v, sh_w);

    // ---- Epilogue ----
    float* ob = out + (size_t)b * STR;

    float* o30 = ob + OFF3 + (size_t)(2 * bx)     * LVL2;
    float* o31 = ob + OFF3 + (size_t)(2 * bx + 1) * LVL2;
#pragma unroll
    for (int jp = 0; jp < 2; ++jp) {
        float2 a00 = unpk(acc0[jp][0]), a01 = unpk(acc0[jp][1]);
        float2 a02 = unpk(acc0[jp][2]), a03 = unpk(acc0[jp][3]);
        float2 b00 = unpk(acc1[jp][0]), b01 = unpk(acc1[jp][1]);
        float2 b02 = unpk(acc1[jp][2]), b03 = unpk(acc1[jp][3]);
        const int jlo = j0 + 2 * jp, jhi = jlo + 1;
        *(float4*)&o30[jlo * C + k0] = make_float4(a00.x, a01.x, a02.x, a03.x);
        *(float4*)&o30[jhi * C + k0] = make_float4(a00.y, a01.y, a02.y, a03.y);
        *(float4*)&o31[jlo * C + k0] = make_float4(b00.x, b01.x, b02.x, b03.x);
        *(float4*)&o31[jhi * C + k0] = make_float4(b00.y, b01.y, b02.y, b03.y);
    }

    if (tid < 2 * C) {
        ob[OFF2 + i_r * C + jj] = S2;            // level 2, rows i0/i1
        if (bx == 0 && r == 0) {
            // p_j now holds path[b][127][jj]
            ob[jj] = p_j - pb[jj];               // level 1
        }
    }
}

extern "C" void kernel_launch(void* const* d_in, const int* in_sizes, int n_in,
                              void* d_out, int out_size)
{
    (void)in_sizes; (void)n_in; (void)out_size;
    const float* path = (const float*)d_in[0];
    float* out = (float*)d_out;
    dim3 grid(C / 2, NB);   // (i-pairs, batch) = (24, 32)
    dim3 block(144);
    sig_depth3_kernel<<<grid, block>>>(path, out);
}

// round 6
// speedup vs baseline: 1.0599x; 1.0599x over previous
#include <cuda_runtime.h>

// Path signature, depth 3. path: (32, 128, 48) fp32. Out: 32 x 112944.
//
// S3[i,j,k] = sum_t w[i][t][j] * v[t][k]
//   v[t][j]    = path[t+1][j] - path[t][j]
//   w[i][t][j] = S2prev[i][j] + (0.5*S1prev[i] + v[t][i]/6) * v[t][j]
//   S2[i][j]  += (S1prev[i] + 0.5*v[t][i]) * v[t][j]
//
// Block (bx,b): two i-planes, two 48x48 (j,k) reg tiles, 144 threads,
// 4x4 per thread per plane, packed fma.rn.f32x2 along j.
// SOFTWARE PIPELINE: producers (threads 0..95) compute chunk s+1's v/w
// right after the stage barrier, BEFORE joining phase B of chunk s, so the
// serial phase-A chain hides under phase-B issue. Double-buffered shared,
// one barrier per stage.

#define NB     32
#define LPATH  128
#define C      48
#define NSTEPS (LPATH - 1)          // 127
#define LVL2   (C * C)
#define LVL3   (C * C * C)
#define STR    (C + LVL2 + LVL3)    // 112944
#define OFF2   C
#define OFF3   (C + LVL2)
#define TCH    8
#define NFULL  15                   // 15 chunks of 8 + tail of 7
#define TAILT  (NSTEPS - NFULL * TCH)   // 7

typedef unsigned long long u64;

__device__ __forceinline__ void ffma2(u64& d, u64 a, u64 b) {
    asm("fma.rn.f32x2 %0, %1, %2, %0;" : "+l"(d) : "l"(a), "l"(b));
}
__device__ __forceinline__ u64 dup_f32(float x) {
    u64 r;
    asm("mov.b64 %0, {%1, %1};" : "=l"(r) : "f"(x));
    return r;
}
__device__ __forceinline__ float2 unpk(u64 a) {
    float2 r;
    asm("mov.b64 {%0, %1}, %2;" : "=f"(r.x), "=f"(r.y) : "l"(a));
    return r;
}

// Phase A: producer thread (tid < 96) computes v/w for T steps of one chunk.
template<int T>
__device__ __forceinline__ void phase_a(
    const float* __restrict__ pb, int base_t, int buf, int i_r, int r, int jj,
    float& p_j, float& p_i, float p0_i, float& S2,
    float (*sh_v)[TCH][C], float (*sh_w)[2][TCH][C])
{
#pragma unroll
    for (int t = 0; t < T; ++t) {
        const float pn_j = pb[(base_t + t + 1) * C + jj];  // coalesced
        const float pn_i = pb[(base_t + t + 1) * C + i_r]; // broadcast
        const float v_j = pn_j - p_j;
        const float v_i = pn_i - p_i;
        const float s1  = p_i - p0_i;
        if (r == 0) sh_v[buf][t][jj] = v_j;
        sh_w[buf][r][t][jj] = fmaf(fmaf(1.0f / 6.0f, v_i, 0.5f * s1), v_j, S2);
        S2 = fmaf(fmaf(0.5f, v_i, s1), v_j, S2);
        p_j = pn_j;
        p_i = pn_i;
    }
}

// Phase B: all threads, T rank-1 updates of both 4x4 tiles (f32x2 packed).
template<int T>
__device__ __forceinline__ void phase_b(
    int buf, int j0, int k0, u64 (&acc0)[2][4], u64 (&acc1)[2][4],
    float (*sh_v)[TCH][C], float (*sh_w)[2][TCH][C])
{
#pragma unroll 4
    for (int t = 0; t < T; ++t) {
        const ulonglong2 w0 = *(const ulonglong2*)&sh_w[buf][0][t][j0];
        const ulonglong2 w1 = *(const ulonglong2*)&sh_w[buf][1][t][j0];
        const float4     vv = *(const float4*)&sh_v[buf][t][k0];
        const u64 vp[4] = { dup_f32(vv.x), dup_f32(vv.y),
                            dup_f32(vv.z), dup_f32(vv.w) };
        const u64 wa[2] = { w0.x, w0.y };
        const u64 wb[2] = { w1.x, w1.y };
#pragma unroll
        for (int jp = 0; jp < 2; ++jp)
#pragma unroll
            for (int kx = 0; kx < 4; ++kx) {
                ffma2(acc0[jp][kx], wa[jp], vp[kx]);
                ffma2(acc1[jp][kx], wb[jp], vp[kx]);
            }
    }
}

__global__ __launch_bounds__(144, 6)
void sig_depth3_kernel(const float* __restrict__ path, float* __restrict__ out)
{
    const int bx  = blockIdx.x;   // 0..23 -> i0 = 2bx, i1 = 2bx+1
    const int b   = blockIdx.y;   // 0..31
    const int tid = threadIdx.x;  // 0..143

    __shared__ __align__(16) float sh_v[2][TCH][C];
    __shared__ __align__(16) float sh_w[2][2][TCH][C];

    const float* pb = path + (size_t)b * LPATH * C;

    u64 acc0[2][4], acc1[2][4];
#pragma unroll
    for (int jp = 0; jp < 2; ++jp)
#pragma unroll
        for (int kx = 0; kx < 4; ++kx) { acc0[jp][kx] = 0ull; acc1[jp][kx] = 0ull; }

    const int j0 = (tid / 12) * 4;
    const int k0 = (tid % 12) * 4;

    const bool prod = (tid < 2 * C);
    const int r   = (tid < C) ? 0 : 1;
    const int jj  = prod ? (tid - r * C) : 0;
    const int i_r = 2 * bx + r;

    float p_j = 0.0f, p_i = 0.0f, p0_i = 0.0f, S2 = 0.0f;
    if (prod) {
        p_j  = pb[jj];
        p0_i = pb[i_r];
        p_i  = p0_i;
    }

    // ---- Pipelined mainloop: A(s+1) issued before B(s) ----
    if (prod) phase_a<TCH>(pb, 0, 0, i_r, r, jj, p_j, p_i, p0_i, S2, sh_v, sh_w);
    __syncthreads();

#pragma unroll 1
    for (int s = 0; s < NFULL - 1; ++s) {     // s = 0..13
        if (prod) phase_a<TCH>(pb, (s + 1) * TCH, (s + 1) & 1, i_r, r, jj,
                               p_j, p_i, p0_i, S2, sh_v, sh_w);
        phase_b<TCH>(s & 1, j0, k0, acc0, acc1, sh_v, sh_w);
        __syncthreads();
    }
    // s = 14: produce tail chunk (7 steps), consume chunk 14
    if (prod) phase_a<TAILT>(pb, NFULL * TCH, NFULL & 1, i_r, r, jj,
                             p_j, p_i, p0_i, S2, sh_v, sh_w);
    phase_b<TCH>((NFULL - 1) & 1, j0, k0, acc0, acc1, sh_v, sh_w);
    __syncthreads();
    // consume tail
    phase_b<TAILT>(NFULL & 1, j0, k0, acc0, acc1, sh_v, sh_w);

    // ---- Epilogue ----
    float* ob = out + (size_t)b * STR;

    float* o30 = ob + OFF3 + (size_t)(2 * bx)     * LVL2;
    float* o31 = ob + OFF3 + (size_t)(2 * bx + 1) * LVL2;
#pragma unroll
    for (int jp = 0; jp < 2; ++jp) {
        float2 a00 = unpk(acc0[jp][0]), a01 = unpk(acc0[jp][1]);
        float2 a02 = unpk(acc0[jp][2]), a03 = unpk(acc0[jp][3]);
        float2 b00 = unpk(acc1[jp][0]), b01 = unpk(acc1[jp][1]);
        float2 b02 = unpk(acc1[jp][2]), b03 = unpk(acc1[jp][3]);
        const int jlo = j0 + 2 * jp, jhi = jlo + 1;
        *(float4*)&o30[jlo * C + k0] = make_float4(a00.x, a01.x, a02.x, a03.x);
        *(float4*)&o30[jhi * C + k0] = make_float4(a00.y, a01.y, a02.y, a03.y);
        *(float4*)&o31[jlo * C + k0] = make_float4(b00.x, b01.x, b02.x, b03.x);
        *(float4*)&o31[jhi * C + k0] = make_float4(b00.y, b01.y, b02.y, b03.y);
    }

    if (prod) {
        ob[OFF2 + i_r * C + jj] = S2;            // level 2, rows i0/i1
        if (bx == 0 && r == 0) {
            // p_j now holds path[b][127][jj]
            ob[jj] = p_j - pb[jj];               // level 1
        }
    }
}

extern "C" void kernel_launch(void* const* d_in, const int* in_sizes, int n_in,
                              void* d_out, int out_size)
{
    (void)in_sizes; (void)n_in; (void)out_size;
    const float* path = (const float*)d_in[0];
    float* out = (float*)d_out;
    dim3 grid(C / 2, NB);   // (i-pairs, batch) = (24, 32)
    dim3 block(144);
    sig_depth3_kernel<<<grid, block>>>(path, out);
}